// round 1
// baseline (speedup 1.0000x reference)
#include <cuda_runtime.h>
#include <cuda_bf16.h>
#include <math.h>

// Problem shape (fixed by the dataset problem)
#define BB 8
#define TT 256
#define UU 64
#define U1 65
#define VV 1024
#define NEGV -1e30f

// Scratch (device globals: no allocation allowed)
__device__ float g_blank[BB * TT * U1];   // lp[b,t,u,0]
__device__ float g_emit [BB * TT * UU];   // lp[b,t,u,labels[b,u]]
__device__ float g_ll   [BB];

// ---------------------------------------------------------------------------
// Phase 1: one warp per (b,t,u) row of V=1024. Single pass over 545 MB.
// ---------------------------------------------------------------------------
__global__ void __launch_bounds__(256) softmax_gather_kernel(
    const float* __restrict__ logits, const int* __restrict__ labels)
{
    const int warp = (blockIdx.x * blockDim.x + threadIdx.x) >> 5;
    const int lane = threadIdx.x & 31;
    const int R = BB * TT * U1;
    if (warp >= R) return;

    const float4* __restrict__ p =
        reinterpret_cast<const float4*>(logits + (size_t)warp * VV);

    // lane loads float4 at index j*32+lane -> elements j*128 + lane*4 + k
    float4 v[8];
#pragma unroll
    for (int j = 0; j < 8; ++j) v[j] = p[j * 32 + lane];

    float mx = -3.4e38f;
#pragma unroll
    for (int j = 0; j < 8; ++j) {
        mx = fmaxf(mx, fmaxf(fmaxf(v[j].x, v[j].y), fmaxf(v[j].z, v[j].w)));
    }
#pragma unroll
    for (int o = 16; o; o >>= 1) mx = fmaxf(mx, __shfl_xor_sync(0xffffffffu, mx, o));

    float s = 0.f;
#pragma unroll
    for (int j = 0; j < 8; ++j) {
        s += __expf(v[j].x - mx) + __expf(v[j].y - mx)
           + __expf(v[j].z - mx) + __expf(v[j].w - mx);
    }
#pragma unroll
    for (int o = 16; o; o >>= 1) s += __shfl_xor_sync(0xffffffffu, s, o);

    const float lse = mx + __logf(s);

    if (lane == 0) {
        // element 0 is lane0's v[0].x
        g_blank[warp] = v[0].x - lse;
        const int u = warp % U1;
        if (u < UU) {
            const int bt = warp / U1;
            const int t  = bt % TT;
            const int b  = bt / TT;
            const int lbl = labels[b * UU + u];
            // single 4B reload; row is L1-resident after the pass above
            g_emit[(b * TT + t) * UU + u] =
                __ldg(&logits[(size_t)warp * VV + lbl]) - lse;
        }
    }
}

// ---------------------------------------------------------------------------
// Phase 2: anti-diagonal wavefront DP. One CTA per batch, 96 threads
// (u = 0..64 active). alpha[t][u] = logaddexp(alpha[t-1][u] + blank[t-1][u],
//                                             alpha[t][u-1] + emit[t][u-1])
// ---------------------------------------------------------------------------
__device__ __forceinline__ float laddexp(float a, float b)
{
    float mx = fmaxf(a, b);
    float mn = fminf(a, b);
    return mx + log1pf(__expf(mn - mx));
}

__global__ void __launch_bounds__(96) rnnt_dp_kernel(
    const int* __restrict__ f_len, const int* __restrict__ y_len)
{
    const int b = blockIdx.x;
    const int u = threadIdx.x;

    __shared__ float sa[2][U1];

    const float* __restrict__ Bk = g_blank + b * TT * U1;
    const float* __restrict__ Em = g_emit  + b * TT * UU;
    const int fl = f_len[b] - 1;   // last valid t
    const int yl = y_len[b];       // target u

    if (u < U1) sa[0][u] = (u == 0) ? 0.f : NEGV;
    __syncthreads();

    for (int d = 1; d <= (TT - 1) + UU; ++d) {
        const int p = (d - 1) & 1;
        if (u < U1) {
            const int t = d - u;
            float val = NEGV;
            if (t >= 0 && t < TT) {
                float up   = (t >= 1) ? sa[p][u]     + Bk[(t - 1) * U1 + u]  : NEGV;
                float left = (u >= 1) ? sa[p][u - 1] + Em[t * UU + (u - 1)]  : NEGV;
                val = laddexp(up, left);
                if (t == fl && u == yl) {
                    g_ll[b] = val + Bk[t * U1 + u];
                }
            }
            sa[1 - p][u] = val;
        }
        __syncthreads();
    }
}

// ---------------------------------------------------------------------------
// Phase 3: out = -mean(ll)
// ---------------------------------------------------------------------------
__global__ void final_kernel(float* __restrict__ out)
{
    if (threadIdx.x == 0) {
        float s = 0.f;
#pragma unroll
        for (int b = 0; b < BB; ++b) s += g_ll[b];
        out[0] = -s / (float)BB;
    }
}

// ---------------------------------------------------------------------------
extern "C" void kernel_launch(void* const* d_in, const int* in_sizes, int n_in,
                              void* d_out, int out_size)
{
    const float* logits = (const float*)d_in[0];
    const int*   labels = (const int*)  d_in[1];
    const int*   f_len  = (const int*)  d_in[2];
    const int*   y_len  = (const int*)  d_in[3];
    float*       out    = (float*)d_out;

    const int R = BB * TT * U1;               // 133120 rows
    const int warps_per_block = 8;            // 256 threads
    const int blocks = (R + warps_per_block - 1) / warps_per_block;

    softmax_gather_kernel<<<blocks, 256>>>(logits, labels);
    rnnt_dp_kernel<<<BB, 96>>>(f_len, y_len);
    final_kernel<<<1, 32>>>(out);
}

// round 2
// speedup vs baseline: 1.4042x; 1.4042x over previous
#include <cuda_runtime.h>
#include <cuda_bf16.h>
#include <math.h>

// Problem shape (fixed by the dataset problem)
#define BB 8
#define TT 256
#define UU 64
#define U1 65
#define VV 1024
#define NEGV -1e30f
#define LN2F 0.6931471805599453f
#define INVLN2F 1.4426950408889634f

// Scratch (device globals: no allocation allowed)
__device__ float g_blank[BB * TT * U1];   // lp[b,t,u,0] * 1/ln2  (log2 domain)
__device__ float g_emit [BB * TT * UU];   // lp[b,t,u,labels[b,u]] * 1/ln2
__device__ float g_ll   [BB];             // log2-domain per-batch ll
__device__ int   g_cnt = 0;

// ---------------------------------------------------------------------------
// Phase 1: one warp per (b,t,u) row of V=1024. Single pass over 545 MB.
// ---------------------------------------------------------------------------
__global__ void __launch_bounds__(256) softmax_gather_kernel(
    const float* __restrict__ logits, const int* __restrict__ labels)
{
    const int warp = (blockIdx.x * blockDim.x + threadIdx.x) >> 5;
    const int lane = threadIdx.x & 31;
    const int R = BB * TT * U1;
    if (warp >= R) return;

    const float4* __restrict__ p =
        reinterpret_cast<const float4*>(logits + (size_t)warp * VV);

    float4 v[8];
#pragma unroll
    for (int j = 0; j < 8; ++j) v[j] = p[j * 32 + lane];

    float mx = -3.4e38f;
#pragma unroll
    for (int j = 0; j < 8; ++j)
        mx = fmaxf(mx, fmaxf(fmaxf(v[j].x, v[j].y), fmaxf(v[j].z, v[j].w)));
#pragma unroll
    for (int o = 16; o; o >>= 1) mx = fmaxf(mx, __shfl_xor_sync(0xffffffffu, mx, o));

    float s = 0.f;
#pragma unroll
    for (int j = 0; j < 8; ++j)
        s += __expf(v[j].x - mx) + __expf(v[j].y - mx)
           + __expf(v[j].z - mx) + __expf(v[j].w - mx);
#pragma unroll
    for (int o = 16; o; o >>= 1) s += __shfl_xor_sync(0xffffffffu, s, o);

    const float lse = mx + __logf(s);

    if (lane == 0) {
        g_blank[warp] = (v[0].x - lse) * INVLN2F;   // log2 domain
        const int u = warp % U1;
        if (u < UU) {
            const int bt = warp / U1;
            const int t  = bt % TT;
            const int b  = bt / TT;
            const int lbl = labels[b * UU + u];
            g_emit[(b * TT + t) * UU + u] =
                (__ldg(&logits[(size_t)warp * VV + lbl]) - lse) * INVLN2F;
        }
    }
}

// ---------------------------------------------------------------------------
// Phase 2: single-warp anti-diagonal wavefront DP, register-resident,
// software-pipelined global loads (depth 4), log2-domain logaddexp.
// ---------------------------------------------------------------------------
__device__ __forceinline__ float ex2a(float x) {
    float y; asm("ex2.approx.f32 %0, %1;" : "=f"(y) : "f"(x)); return y;
}
__device__ __forceinline__ float lg2a(float x) {
    float y; asm("lg2.approx.f32 %0, %1;" : "=f"(y) : "f"(x)); return y;
}
// logaddexp in base-2 domain
__device__ __forceinline__ float ladd2(float a, float b) {
    float mx = fmaxf(a, b);
    float mn = fminf(a, b);
    return mx + lg2a(1.0f + ex2a(mn - mx));
}

struct LS { float b0, e0, b1, e1, bx, ex; };

__device__ __forceinline__ LS load_diag(
    const float* __restrict__ Bk, const float* __restrict__ Em,
    int d, int u0, int u1, bool lane31)
{
    LS r;
    const int t0 = d - u0, t1 = d - u1, tx = d - 64;
    r.b0 = (t0 >= 1 && t0 < TT)            ? __ldg(Bk + (t0 - 1) * U1 + u0) : NEGV;
    r.e0 = (t0 >= 0 && t0 < TT && u0 >= 1) ? __ldg(Em + t0 * UU + (u0 - 1)) : NEGV;
    r.b1 = (t1 >= 1 && t1 < TT)            ? __ldg(Bk + (t1 - 1) * U1 + u1) : NEGV;
    r.e1 = (t1 >= 0 && t1 < TT)            ? __ldg(Em + t1 * UU + (u1 - 1)) : NEGV;
    r.bx = (lane31 && tx >= 1 && tx < TT)  ? __ldg(Bk + (tx - 1) * U1 + 64) : NEGV;
    r.ex = (lane31 && tx >= 0 && tx < TT)  ? __ldg(Em + tx * UU + 63)       : NEGV;
    return r;
}

__global__ void __launch_bounds__(32) rnnt_dp_kernel(
    const int* __restrict__ f_len, const int* __restrict__ y_len,
    float* __restrict__ out)
{
    const int b = blockIdx.x;
    const int L = threadIdx.x;
    const bool lane31 = (L == 31);

    const float* __restrict__ Bk = g_blank + b * TT * U1;
    const float* __restrict__ Em = g_emit  + b * TT * UU;
    const int fl = f_len[b] - 1;   // last valid t
    const int yl = y_len[b];       // target u
    const int dtarget = fl + yl;
    const float bkfin = __ldg(Bk + fl * U1 + yl);

    const int u0 = 2 * L, u1 = 2 * L + 1;

    // alpha registers for previous diagonal
    float a0 = (L == 0) ? 0.f : NEGV;  // u = 2L
    float a1 = NEGV;                    // u = 2L+1
    float ax = NEGV;                    // u = 64 (lane 31)

    LS s0 = load_diag(Bk, Em, 1, u0, u1, lane31);
    LS s1 = load_diag(Bk, Em, 2, u0, u1, lane31);
    LS s2 = load_diag(Bk, Em, 3, u0, u1, lane31);
    LS s3 = load_diag(Bk, Em, 4, u0, u1, lane31);

#define STEP(D, S)                                                          \
    {                                                                       \
        float a1m = __shfl_up_sync(0xffffffffu, a1, 1);                     \
        float up0 = a0 + (S).b0;                                            \
        float lf0 = a1m + (S).e0;                                           \
        float up1 = a1 + (S).b1;                                            \
        float lf1 = a0 + (S).e1;                                            \
        float upx = ax + (S).bx;                                            \
        float lfx = a1 + (S).ex;                                            \
        float n0 = ladd2(up0, lf0);                                         \
        float n1 = ladd2(up1, lf1);                                         \
        float nx = ladd2(upx, lfx);                                         \
        if ((D) == dtarget) {                                               \
            if (u0 == yl)                g_ll[b] = n0 + bkfin;              \
            else if (u1 == yl)           g_ll[b] = n1 + bkfin;              \
            else if (lane31 && yl == 64) g_ll[b] = nx + bkfin;              \
        }                                                                   \
        a0 = n0; a1 = n1; ax = nx;                                          \
    }

    // diagonals 1..320 (320 is a harmless no-op diagonal; keeps trip fixed)
    for (int d = 1; d <= 320; d += 4) {
        STEP(d,     s0); s0 = load_diag(Bk, Em, d + 4, u0, u1, lane31);
        STEP(d + 1, s1); s1 = load_diag(Bk, Em, d + 5, u0, u1, lane31);
        STEP(d + 2, s2); s2 = load_diag(Bk, Em, d + 6, u0, u1, lane31);
        STEP(d + 3, s3); s3 = load_diag(Bk, Em, d + 7, u0, u1, lane31);
    }
#undef STEP

    // last-CTA reduction: out = -mean(ll) (convert log2 -> ln)
    __threadfence();
    __syncwarp();
    if (L == 0) {
        int done = atomicAdd(&g_cnt, 1);
        if (done == BB - 1) {
            float s = 0.f;
#pragma unroll
            for (int i = 0; i < BB; ++i) s += g_ll[i];
            out[0] = -(s * LN2F) / (float)BB;
            g_cnt = 0;   // reset for next replay (deterministic)
        }
    }
}

// ---------------------------------------------------------------------------
extern "C" void kernel_launch(void* const* d_in, const int* in_sizes, int n_in,
                              void* d_out, int out_size)
{
    const float* logits = (const float*)d_in[0];
    const int*   labels = (const int*)  d_in[1];
    const int*   f_len  = (const int*)  d_in[2];
    const int*   y_len  = (const int*)  d_in[3];
    float*       out    = (float*)d_out;

    const int R = BB * TT * U1;               // 133120 rows
    const int warps_per_block = 8;            // 256 threads
    const int blocks = (R + warps_per_block - 1) / warps_per_block;

    softmax_gather_kernel<<<blocks, 256>>>(logits, labels);
    rnnt_dp_kernel<<<BB, 32>>>(f_len, y_len, out);
}

// round 3
// speedup vs baseline: 1.8741x; 1.3347x over previous
#include <cuda_runtime.h>
#include <cuda_bf16.h>
#include <math.h>

// Problem shape (fixed by the dataset problem)
#define BB 8
#define TT 256
#define UU 64
#define U1 65
#define VV 1024
#define DD 320            // diagonals d = t+u, 0..319
#define PITCH 66          // row pitch (floats) for diagonal-major layout
#define NEGV -1e30f
#define LN2F 0.6931471805599453f
#define INVLN2F 1.4426950408889634f

// Scratch (device globals: no allocation allowed). Zero-initialized at load;
// slots never written by phase 1 stay 0.0, which is harmless (paired with
// ~-1e30 alpha terms).
__device__ float g_bT[BB * DD * PITCH];   // blank(t,u)*INVLN2 at [b][t+u][u]
__device__ float g_eT[BB * DD * PITCH];   // emit (t,u)*INVLN2 at [b][t+u][u]
__device__ float g_ll[BB];
__device__ int   g_cnt = 0;

// ---------------------------------------------------------------------------
// Phase 1: one warp per (b,t,u) row of V=1024. Single pass over 545 MB.
// Writes blank/emit into diagonal-major transposed layout (log2 domain).
// ---------------------------------------------------------------------------
__global__ void __launch_bounds__(256) softmax_gather_kernel(
    const float* __restrict__ logits, const int* __restrict__ labels)
{
    const int warp = (blockIdx.x * blockDim.x + threadIdx.x) >> 5;
    const int lane = threadIdx.x & 31;
    const int R = BB * TT * U1;
    if (warp >= R) return;

    const float4* __restrict__ p =
        reinterpret_cast<const float4*>(logits + (size_t)warp * VV);

    float4 v[8];
#pragma unroll
    for (int j = 0; j < 8; ++j) v[j] = p[j * 32 + lane];

    float mx = -3.4e38f;
#pragma unroll
    for (int j = 0; j < 8; ++j)
        mx = fmaxf(mx, fmaxf(fmaxf(v[j].x, v[j].y), fmaxf(v[j].z, v[j].w)));
#pragma unroll
    for (int o = 16; o; o >>= 1) mx = fmaxf(mx, __shfl_xor_sync(0xffffffffu, mx, o));

    float s = 0.f;
#pragma unroll
    for (int j = 0; j < 8; ++j)
        s += __expf(v[j].x - mx) + __expf(v[j].y - mx)
           + __expf(v[j].z - mx) + __expf(v[j].w - mx);
#pragma unroll
    for (int o = 16; o; o >>= 1) s += __shfl_xor_sync(0xffffffffu, s, o);

    const float lse = mx + __logf(s);

    if (lane == 0) {
        const int u  = warp % U1;
        const int bt = warp / U1;
        const int t  = bt % TT;
        const int b  = bt / TT;
        const int base = (b * DD + (t + u)) * PITCH + u;
        g_bT[base] = (v[0].x - lse) * INVLN2F;
        if (u < UU) {
            const int lbl = labels[b * UU + u];
            g_eT[base] =
                (__ldg(&logits[(size_t)warp * VV + lbl]) - lse) * INVLN2F;
        }
    }
}

// ---------------------------------------------------------------------------
// Phase 2: single-warp anti-diagonal wavefront DP, register-resident,
// diagonal-contiguous loads, software-pipelined (depth 4), log2 logaddexp.
// ---------------------------------------------------------------------------
__device__ __forceinline__ float ex2a(float x) {
    float y; asm("ex2.approx.f32 %0, %1;" : "=f"(y) : "f"(x)); return y;
}
__device__ __forceinline__ float lg2a(float x) {
    float y; asm("lg2.approx.f32 %0, %1;" : "=f"(y) : "f"(x)); return y;
}
__device__ __forceinline__ float ladd2(float a, float b) {
    float mx = fmaxf(a, b);
    float mn = fminf(a, b);
    return mx + lg2a(1.0f + ex2a(mn - mx));
}

struct LS { float b0, b1, e0, e1, bx, ex; };

// Load the operand row (diagonal d-1) for computing diagonal d.
__device__ __forceinline__ LS load_diag(
    const float* __restrict__ bT, const float* __restrict__ eT, int d, int L)
{
    int dm = d - 1; if (dm > DD - 1) dm = DD - 1;   // clamp OOB prefetch
    const float* br = bT + dm * PITCH;
    const float* er = eT + dm * PITCH;
    LS r;
    float2 bv = __ldg(reinterpret_cast<const float2*>(br) + L); // b[2L],b[2L+1]
    r.b0 = bv.x;
    r.b1 = bv.y;
    int j0 = 2 * L - 1; if (j0 < 0) j0 = 0;
    r.e0 = __ldg(er + j0);        // e[2L-1] (lane0 value unused)
    r.e1 = __ldg(er + 2 * L);     // e[2L]
    r.bx = __ldg(br + 64);        // broadcast
    r.ex = __ldg(er + 63);        // broadcast
    return r;
}

__global__ void __launch_bounds__(32) rnnt_dp_kernel(
    const int* __restrict__ f_len, const int* __restrict__ y_len,
    float* __restrict__ out)
{
    const int b = blockIdx.x;
    const int L = threadIdx.x;

    const float* __restrict__ bT = g_bT + b * DD * PITCH;
    const float* __restrict__ eT = g_eT + b * DD * PITCH;
    const int fl = f_len[b] - 1;        // last valid t
    const int yl = y_len[b];            // target u
    const int dtarget = fl + yl;
    const float bkfin = __ldg(bT + dtarget * PITCH + yl);  // blank(fl,yl)

    const int u0 = 2 * L, u1 = 2 * L + 1;

    // alpha registers (previous diagonal): u0=2L, u1=2L+1, ux=64 (lane31)
    float a0 = (L == 0) ? 0.f : NEGV;
    float a1 = NEGV;
    float ax = NEGV;

    LS s0 = load_diag(bT, eT, 1, L);
    LS s1 = load_diag(bT, eT, 2, L);
    LS s2 = load_diag(bT, eT, 3, L);
    LS s3 = load_diag(bT, eT, 4, L);

#define STEP(D, S)                                                          \
    {                                                                       \
        float a1m = __shfl_up_sync(0xffffffffu, a1, 1);                     \
        float up0 = a0 + (S).b0;                                            \
        float lf0 = (L == 0) ? NEGV : a1m + (S).e0;                         \
        float up1 = a1 + (S).b1;                                            \
        float lf1 = a0 + (S).e1;                                            \
        float upx = ax + (S).bx;                                            \
        float lfx = a1 + (S).ex;                                            \
        float n0 = ladd2(up0, lf0);                                         \
        float n1 = ladd2(up1, lf1);                                         \
        float nx = ladd2(upx, lfx);                                         \
        if ((D) == dtarget) {                                               \
            if (u0 == yl)                 g_ll[b] = n0 + bkfin;             \
            else if (u1 == yl)            g_ll[b] = n1 + bkfin;             \
            else if (yl == 64 && L == 31) g_ll[b] = nx + bkfin;             \
        }                                                                   \
        a0 = n0; a1 = n1; ax = nx;                                          \
    }

    // diagonals 1..320 (320 is a harmless extra; dtarget <= 319)
    for (int d = 1; d <= 317; d += 4) {
        STEP(d,     s0); s0 = load_diag(bT, eT, d + 4, L);
        STEP(d + 1, s1); s1 = load_diag(bT, eT, d + 5, L);
        STEP(d + 2, s2); s2 = load_diag(bT, eT, d + 6, L);
        STEP(d + 3, s3); s3 = load_diag(bT, eT, d + 7, L);
    }
#undef STEP

    // last-CTA reduction: out = -mean(ll) (convert log2 -> ln)
    __threadfence();
    __syncwarp();
    if (L == 0) {
        int done = atomicAdd(&g_cnt, 1);
        if (done == BB - 1) {
            float s = 0.f;
#pragma unroll
            for (int i = 0; i < BB; ++i) s += g_ll[i];
            out[0] = -(s * LN2F) / (float)BB;
            g_cnt = 0;   // reset for next graph replay
        }
    }
}

// ---------------------------------------------------------------------------
extern "C" void kernel_launch(void* const* d_in, const int* in_sizes, int n_in,
                              void* d_out, int out_size)
{
    const float* logits = (const float*)d_in[0];
    const int*   labels = (const int*)  d_in[1];
    const int*   f_len  = (const int*)  d_in[2];
    const int*   y_len  = (const int*)  d_in[3];
    float*       out    = (float*)d_out;

    const int R = BB * TT * U1;               // 133120 rows
    const int warps_per_block = 8;            // 256 threads
    const int blocks = (R + warps_per_block - 1) / warps_per_block;

    softmax_gather_kernel<<<blocks, 256>>>(logits, labels);
    rnnt_dp_kernel<<<BB, 32>>>(f_len, y_len, out);
}

// round 6
// speedup vs baseline: 2.4816x; 1.3241x over previous
#include <cuda_runtime.h>
#include <cuda_bf16.h>
#include <cstdint>
#include <stdint.h>
#include <math.h>

// Problem shape (fixed by the dataset problem)
#define BB 8
#define TT 256
#define UU 64
#define U1 65
#define VV 1024
#define DD 320            // diagonals d = t+u, 0..319
#define PITCH 66          // row pitch (floats) for diagonal-major layout
#define CH 32             // diagonals per smem chunk
#define NC (DD / CH)      // 10 chunks
#define NEGV -1e30f
#define LN2F 0.6931471805599453f
#define INVLN2F 1.4426950408889634f

// Scratch (device globals: no allocation allowed). Zero-initialized at load;
// slots never written by phase 1 stay 0.0, which is harmless.
__device__ __align__(16) float g_bT[BB * DD * PITCH]; // blank(t,u)/ln2 at [b][t+u][u]
__device__ __align__(16) float g_eT[BB * DD * PITCH]; // emit (t,u)/ln2 at [b][t+u][u]
__device__ float g_ll[BB];
__device__ int   g_cnt = 0;

// ---------------------------------------------------------------------------
// Phase 1: one warp per (b,t,u) row of V=1024. Single pass over 545 MB.
// Writes blank/emit into diagonal-major transposed layout (log2 domain).
// ---------------------------------------------------------------------------
__global__ void __launch_bounds__(256) softmax_gather_kernel(
    const float* __restrict__ logits, const int* __restrict__ labels)
{
    const int warp = (blockIdx.x * blockDim.x + threadIdx.x) >> 5;
    const int lane = threadIdx.x & 31;
    const int R = BB * TT * U1;
    if (warp >= R) return;

    const float4* __restrict__ p =
        reinterpret_cast<const float4*>(logits + (size_t)warp * VV);

    float4 v[8];
#pragma unroll
    for (int j = 0; j < 8; ++j) v[j] = p[j * 32 + lane];

    float mx = -3.4e38f;
#pragma unroll
    for (int j = 0; j < 8; ++j)
        mx = fmaxf(mx, fmaxf(fmaxf(v[j].x, v[j].y), fmaxf(v[j].z, v[j].w)));
#pragma unroll
    for (int o = 16; o; o >>= 1) mx = fmaxf(mx, __shfl_xor_sync(0xffffffffu, mx, o));

    float s = 0.f;
#pragma unroll
    for (int j = 0; j < 8; ++j)
        s += __expf(v[j].x - mx) + __expf(v[j].y - mx)
           + __expf(v[j].z - mx) + __expf(v[j].w - mx);
#pragma unroll
    for (int o = 16; o; o >>= 1) s += __shfl_xor_sync(0xffffffffu, s, o);

    const float lse = mx + __logf(s);

    if (lane == 0) {
        const int u  = warp % U1;
        const int bt = warp / U1;
        const int t  = bt % TT;
        const int b  = bt / TT;
        const int base = (b * DD + (t + u)) * PITCH + u;
        g_bT[base] = (v[0].x - lse) * INVLN2F;
        if (u < UU) {
            const int lbl = labels[b * UU + u];
            g_eT[base] =
                (__ldg(&logits[(size_t)warp * VV + lbl]) - lse) * INVLN2F;
        }
    }
}

// ---------------------------------------------------------------------------
// Phase 2: warp-specialized DP. Warp 0 computes the wavefront from smem;
// warps 1-3 cp.async the next chunk of diagonals into a ping-pong buffer.
// ---------------------------------------------------------------------------
__device__ __forceinline__ float ex2a(float x) {
    float y; asm("ex2.approx.f32 %0, %1;" : "=f"(y) : "f"(x)); return y;
}
__device__ __forceinline__ float lg2a(float x) {
    float y; asm("lg2.approx.f32 %0, %1;" : "=f"(y) : "f"(x)); return y;
}
__device__ __forceinline__ float ladd2(float a, float b) {
    float mx = fmaxf(a, b);
    float mn = fminf(a, b);
    return mx + lg2a(1.0f + ex2a(mn - mx));
}

__device__ __forceinline__ void cp16(unsigned int saddr, const void* gaddr)
{
    asm volatile("cp.async.cg.shared.global [%0], [%1], 16;"
                 :: "r"(saddr), "l"(gaddr));
}

#define CHUNK_F4 ((CH * PITCH) / 4)   // 528 float4 per array per chunk

// Producer: copy chunk c (32 diagonals of both arrays) into buffer `buf`.
__device__ __forceinline__ void issue_chunk(
    const float* __restrict__ bT, const float* __restrict__ eT,
    float* sb_buf, float* se_buf, int c, int ptid)
{
    const float4* gb = reinterpret_cast<const float4*>(bT) + c * CHUNK_F4;
    const float4* ge = reinterpret_cast<const float4*>(eT) + c * CHUNK_F4;
    unsigned int sb_a = (unsigned int)__cvta_generic_to_shared(sb_buf);
    unsigned int se_a = (unsigned int)__cvta_generic_to_shared(se_buf);
#pragma unroll
    for (int i = 0; i < 6; ++i) {
        int idx = ptid + i * 96;
        if (idx < CHUNK_F4) {
            cp16(sb_a + idx * 16, gb + idx);
            cp16(se_a + idx * 16, ge + idx);
        }
    }
    asm volatile("cp.async.commit_group;" ::: "memory");
}

__global__ void __launch_bounds__(128) rnnt_dp_kernel(
    const int* __restrict__ f_len, const int* __restrict__ y_len,
    float* __restrict__ out)
{
    const int b = blockIdx.x;
    const int tid = threadIdx.x;
    const int L = tid & 31;
    const int w = tid >> 5;

    __shared__ __align__(16) float sb[2][CH * PITCH];
    __shared__ __align__(16) float se[2][CH * PITCH];

    const float* __restrict__ bT = g_bT + b * DD * PITCH;
    const float* __restrict__ eT = g_eT + b * DD * PITCH;

    const int fl = f_len[b] - 1;        // last valid t
    const int yl = y_len[b];            // target u
    const int dtarget = fl + yl;
    const float bkfin = __ldg(bT + dtarget * PITCH + yl);  // blank(fl,yl)

    const bool producer = (w > 0);
    const int ptid = tid - 32;          // 0..95 for producers

    if (producer) {
        issue_chunk(bT, eT, sb[0], se[0], 0, ptid);
        asm volatile("cp.async.wait_group 0;" ::: "memory");
    }
    __syncthreads();

    // alpha registers (previous diagonal): u0=2L, u1=2L+1, ux=64 (lane31)
    float a0 = (L == 0) ? 0.f : NEGV;
    float a1 = NEGV;
    float ax = NEGV;

    for (int c = 0; c < NC; ++c) {
        if (producer && c + 1 < NC) {
            issue_chunk(bT, eT, sb[(c + 1) & 1], se[(c + 1) & 1], c + 1, ptid);
        }
        if (w == 0) {
            const float* __restrict__ sbr = sb[c & 1];
            const float* __restrict__ ser = se[c & 1];
            const int dbase = c * CH + 1;   // first diagonal of this chunk
#pragma unroll 4
            for (int dd = 0; dd < CH; ++dd) {
                const float* br = sbr + dd * PITCH;
                const float* er = ser + dd * PITCH;
                float2 bp = *reinterpret_cast<const float2*>(br + 2 * L);
                float2 ep = *reinterpret_cast<const float2*>(er + 2 * L);
                float bx = br[64];

                float t1  = a1 + ep.y;                       // alpha[2L+1]+e[2L+1]
                float lf0 = __shfl_up_sync(0xffffffffu, t1, 1);
                if (L == 0) lf0 = NEGV;
                float up0 = a0 + bp.x;
                float n0  = ladd2(up0, lf0);

                float up1 = a1 + bp.y;
                float lf1 = a0 + ep.x;
                float n1  = ladd2(up1, lf1);

                float upx = ax + bx;
                float nx  = ladd2(upx, t1);   // valid on lane31 only

                const int d = dbase + dd;
                if (d == dtarget) {
                    if (2 * L == yl)              g_ll[b] = n0 + bkfin;
                    else if (2 * L + 1 == yl)     g_ll[b] = n1 + bkfin;
                    else if (yl == 64 && L == 31) g_ll[b] = nx + bkfin;
                }
                a0 = n0; a1 = n1; ax = nx;
            }
        }
        if (producer && c + 1 < NC) {
            asm volatile("cp.async.wait_group 0;" ::: "memory");
        }
        __syncthreads();
    }

    // last-CTA reduction: out = -mean(ll) (convert log2 -> ln)
    __threadfence();
    if (tid == 0) {
        int done = atomicAdd(&g_cnt, 1);
        if (done == BB - 1) {
            float s = 0.f;
#pragma unroll
            for (int i = 0; i < BB; ++i) s += g_ll[i];
            out[0] = -(s * LN2F) / (float)BB;
            g_cnt = 0;   // reset for next graph replay
        }
    }
}

// ---------------------------------------------------------------------------
extern "C" void kernel_launch(void* const* d_in, const int* in_sizes, int n_in,
                              void* d_out, int out_size)
{
    const float* logits = (const float*)d_in[0];
    const int*   labels = (const int*)  d_in[1];
    const int*   f_len  = (const int*)  d_in[2];
    const int*   y_len  = (const int*)  d_in[3];
    float*       out    = (float*)d_out;

    const int R = BB * TT * U1;               // 133120 rows
    const int warps_per_block = 8;            // 256 threads
    const int blocks = (R + warps_per_block - 1) / warps_per_block;

    softmax_gather_kernel<<<blocks, 256>>>(logits, labels);
    rnnt_dp_kernel<<<BB, 128>>>(f_len, y_len, out);
}